// round 9
// baseline (speedup 1.0000x reference)
#include <cuda_runtime.h>
#include <stdint.h>

// Problem shape (fixed by the reference): x is (T, B, 1) fp32, lr scalar.
#define T_DIM 8192
#define B_DIM 4096
#define S_CHUNKS 64
#define CH 128            // T_DIM / S_CHUNKS
#define NWORDS 4          // CH / 32
#define NTILES (B_DIM / 256)   // 16 column tiles of 256

// Scratch (device globals — no allocation allowed).
__device__ float4   g_agg [S_CHUNKS * B_DIM];   // local affine (A0,C0,A1,C1)  4 MB
__device__ float2   g_pre [S_CHUNKS * B_DIM];   // inclusive exit (p0,p1)      2 MB
__device__ unsigned g_flag[S_CHUNKS * NTILES];  // 0=none, 1=agg, 2=prefix
__device__ unsigned g_ticket;

__device__ __forceinline__ float clamp_lr(const float* lrp) {
    return fminf(fmaxf(*lrp, 0.0f), 1.0f);
}

// r^n, n in [0,128], square-and-multiply (no smem, no sync).
__device__ __forceinline__ float rpow_int(float r, int n) {
    float res = 1.0f, base = r;
    #pragma unroll
    for (int i = 0; i < 8; i++) {
        res  = ((n >> i) & 1) ? res * base : res;
        base = base * base;
    }
    return res;
}

__device__ __forceinline__ unsigned ld_acquire(const unsigned* p) {
    unsigned v;
    asm volatile("ld.acquire.gpu.u32 %0, [%1];" : "=r"(v) : "l"(p) : "memory");
    return v;
}
__device__ __forceinline__ void st_release(unsigned* p, unsigned v) {
    asm volatile("st.release.gpu.u32 [%0], %1;" :: "l"(p), "r"(v) : "memory");
}

__global__ void init_kernel() {
    const int i = blockIdx.x * blockDim.x + threadIdx.x;
    if (i < S_CHUNKS * NTILES) g_flag[i] = 0u;
    if (i == 0) g_ticket = 0u;
}

// ---------------------------------------------------------------------------
// Fused single-pass kernel, decoupled look-back (take 3).
// Fixes vs R7: 51-reg ceiling (no 32-reg spill trap), look-back batch of 4
// float4 (16 regs) instead of 8 (32 regs). 5 blocks/SM -> 740/1024 resident;
// s-major tickets keep waiting deadlock-free and let wave-2 READS overlap
// wave-1 WRITES — the read/write overlap the 3-pass structure can never get.
// ---------------------------------------------------------------------------
__global__ void __launch_bounds__(256, 5) fused_kernel(
    const float* __restrict__ x, const float* __restrict__ lrp,
    float* __restrict__ out)
{
    __shared__ unsigned s_ticket;
    __shared__ int      s_jstop;
    if (threadIdx.x == 0) s_ticket = atomicAdd(&g_ticket, 1u);
    __syncthreads();
    const int s  = s_ticket >> 4;            // s-major ticket order
    const int bx = s_ticket & (NTILES - 1);
    const int b  = bx * 256 + threadIdx.x;

    const float lr = clamp_lr(lrp);
    const float r  = 1.0f - lr;

    // ---- Phase 1: stream x chunk once; bits -> W[4]; local affine ----
    const float* xp = x + (size_t)(s * CH) * B_DIM + b;
    const float xprev = (s == 0) ? 0.0f : xp[-(ptrdiff_t)B_DIM];
    bool pb = (xprev != 0.0f);

    float C0 = 0.0f, C1 = 0.0f;
    uint32_t W[NWORDS];

    #pragma unroll
    for (int h = 0; h < NWORDS; h++) {
        uint32_t w = 0;
        #pragma unroll
        for (int i0 = 0; i0 < 32; i0 += 8) {
            float xv[8];                               // 8-deep LDG batch
            #pragma unroll
            for (int j = 0; j < 8; j++)
                xv[j] = xp[(size_t)(h * 32 + i0 + j) * B_DIM];
            #pragma unroll
            for (int j = 0; j < 8; j++) {
                const float v  = xv[j];
                const bool  xb = (v != 0.0f);
                const float t  = v * lr;               // exact: x in {0,1}
                C0 = pb ? C0 : fmaf(C0, r, t);
                C1 = pb ? fmaf(C1, r, t) : C1;
                w  = xb ? (w | (1u << (i0 + j))) : w;
                pb = xb;
            }
        }
        W[h] = w;
    }

    // obs_prev stream over the chunk = [xprev, x_0 .. x_126]
    const int ones = __popc(W[0]) + __popc(W[1]) + __popc(W[2]) + __popc(W[3]);
    const int n1   = ones - (int)(W[3] >> 31) + (xprev != 0.0f ? 1 : 0);
    const float A0 = rpow_int(r, CH - n1);
    const float A1 = rpow_int(r, n1);

    // ---- Publish local aggregate (readers at higher s) ----
    if (s > 0) {
        g_agg[s * B_DIM + b] = make_float4(A0, C0, A1, C1);
        __syncthreads();
        if (threadIdx.x == 0)
            st_release(&g_flag[s * NTILES + bx], 1u);
    }

    // ---- Phase 2: look-back for entry state ----
    float p0, p1;
    if (s == 0) {
        p0 = 0.5f; p1 = 0.5f;
    } else {
        if (threadIdx.x == 0) {
            int j = s - 1;
            for (;;) {
                unsigned v;
                while ((v = ld_acquire(&g_flag[j * NTILES + bx])) == 0u)
                    __nanosleep(32);
                if (v == 2u) break;            // inclusive prefix available
                j--;
            }
            s_jstop = j;
        }
        __syncthreads();
        const int jstop = s_jstop;

        // Compose aggregates j = s-1 .. jstop+1, batch of 4 (16 regs).
        float Aa0 = 1.0f, Ca0 = 0.0f, Aa1 = 1.0f, Ca1 = 0.0f;
        int j = s - 1;
        while (j > jstop) {
            const int nb = min(4, j - jstop);
            float4 agg[4];
            #pragma unroll
            for (int k = 0; k < 4; k++)
                if (k < nb) agg[k] = g_agg[(j - k) * B_DIM + b];
            #pragma unroll
            for (int k = 0; k < 4; k++) {
                if (k < nb) {
                    Ca0 = fmaf(Aa0, agg[k].y, Ca0);  Aa0 *= agg[k].x;
                    Ca1 = fmaf(Aa1, agg[k].w, Ca1);  Aa1 *= agg[k].z;
                }
            }
            j -= nb;
        }
        const float2 base = g_pre[jstop * B_DIM + b];
        p0 = fmaf(Aa0, base.x, Ca0);
        p1 = fmaf(Aa1, base.y, Ca1);
    }

    // ---- Publish inclusive exit (short-circuits later look-backs) ----
    if (s < S_CHUNKS - 1) {
        g_pre[s * B_DIM + b] = make_float2(fmaf(p0, A0, C0), fmaf(p1, A1, C1));
        __syncthreads();
        if (threadIdx.x == 0)
            st_release(&g_flag[s * NTILES + bx], 2u);
    }

    // ---- Phase 3: replay from register bits, stream predictions out ----
    float* op = out + (size_t)(s * CH) * B_DIM + b;
    bool pb2 = (xprev != 0.0f);
    #pragma unroll
    for (int wi = 0; wi < NWORDS; wi++) {
        uint32_t w = W[wi];
        #pragma unroll
        for (int i = 0; i < 32; i++) {
            const bool  xb = (w & 1u);
            w >>= 1;
            const float xv = xb ? 1.0f : 0.0f;
            const float l0 = pb2 ? 0.0f : lr;
            const float l1 = pb2 ? lr   : 0.0f;
            p0 = fmaf(l0, xv - p0, p0);
            p1 = fmaf(l1, xv - p1, p1);
            op[(size_t)(wi * 32 + i) * B_DIM] = xb ? p1 : p0;
            pb2 = xb;
        }
    }
}

extern "C" void kernel_launch(void* const* d_in, const int* in_sizes, int n_in,
                              void* d_out, int out_size)
{
    const float* x  = (const float*)d_in[0];
    const float* lr = (const float*)d_in[1];
    if (n_in >= 2 && in_sizes[0] == 1) { x = (const float*)d_in[1]; lr = (const float*)d_in[0]; }

    init_kernel<<<(S_CHUNKS * NTILES + 255) / 256, 256>>>();
    fused_kernel<<<S_CHUNKS * NTILES, 256>>>(x, lr, (float*)d_out);
}

// round 10
// speedup vs baseline: 1.8158x; 1.8158x over previous
#include <cuda_runtime.h>
#include <stdint.h>

// Problem shape (fixed by the reference): x is (T, B, 1) fp32, lr scalar.
#define T_DIM 8192
#define B_DIM 4096
#define S_CHUNKS 64
#define CH 128          // T_DIM / S_CHUNKS
#define NWORDS 4        // CH / 32

// Scratch (device globals). Chunk-major, coalesced over b.
__device__ float4 g_coef [S_CHUNKS * B_DIM];  // (A0, C0, A1, C1) per (s,b)   4 MB
__device__ uint4  g_bits [S_CHUNKS * B_DIM];  // 128 packed x bits per (s,b)  4 MB
__device__ float  g_xprev[S_CHUNKS * B_DIM];  // x[t0-1] per (s,b)            1 MB
__device__ float2 g_state[S_CHUNKS * B_DIM];  // (p0,p1) entering chunk       2 MB

__device__ __forceinline__ float clamp_lr(const float* lrp) {
    return fminf(fmaxf(*lrp, 0.0f), 1.0f);
}

// r^n, n in [0,128], square-and-multiply (no smem, no syncs).
__device__ __forceinline__ float rpow_int(float r, int n) {
    float res = 1.0f, base = r;
    #pragma unroll
    for (int i = 0; i < 8; i++) {
        res  = ((n >> i) & 1) ? res * base : res;
        base = base * base;
    }
    return res;
}

// ---------------------------------------------------------------------------
// Pass 1 (R4 + __ldcs streaming loads): per (chunk s, column b), one column
// per thread (262144 threads). x has zero reuse -> bypass L2 allocation.
// ---------------------------------------------------------------------------
__global__ void __launch_bounds__(256) pass1_kernel(
    const float* __restrict__ x, const float* __restrict__ lrp)
{
    const int b = blockIdx.x * blockDim.x + threadIdx.x;
    const int s = blockIdx.y;
    const float lr = clamp_lr(lrp);
    const float r  = 1.0f - lr;

    const float* xp = x + (size_t)(s * CH) * B_DIM + b;

    const float xprev = (s == 0) ? 0.0f : __ldcs(xp - B_DIM);
    g_xprev[s * B_DIM + b] = xprev;
    bool pb = (xprev != 0.0f);

    float C0 = 0.0f, C1 = 0.0f;
    uint32_t W[NWORDS];

    #pragma unroll
    for (int h = 0; h < NWORDS; h++) {
        uint32_t w = 0;
        #pragma unroll
        for (int i0 = 0; i0 < 32; i0 += 8) {
            float xv[8];                               // 8-deep LDG batch
            #pragma unroll
            for (int j = 0; j < 8; j++)
                xv[j] = __ldcs(&xp[(size_t)(h * 32 + i0 + j) * B_DIM]);
            #pragma unroll
            for (int j = 0; j < 8; j++) {
                const float v  = xv[j];
                const bool  xb = (v != 0.0f);
                const float t  = v * lr;              // exact: x in {0,1}
                C0 = pb ? C0 : fmaf(C0, r, t);
                C1 = pb ? fmaf(C1, r, t) : C1;
                w  = xb ? (w | (1u << (i0 + j))) : w;
                pb = xb;
            }
        }
        W[h] = w;
    }

    const int ones = __popc(W[0]) + __popc(W[1]) + __popc(W[2]) + __popc(W[3]);
    const int n1   = ones - (int)(W[3] >> 31) + (xprev != 0.0f ? 1 : 0);

    g_coef[s * B_DIM + b] = make_float4(rpow_int(r, CH - n1), C0,
                                        rpow_int(r, n1),      C1);
    g_bits[s * B_DIM + b] = make_uint4(W[0], W[1], W[2], W[3]);
}

// ---------------------------------------------------------------------------
// Scan (R4 verbatim — proven ~3.5us): one thread per column, 64 sequential
// affine compositions; coef data L2-resident after pass1.
// ---------------------------------------------------------------------------
__global__ void __launch_bounds__(256) scan_kernel()
{
    const int b = blockIdx.x * blockDim.x + threadIdx.x;
    float p0 = 0.5f, p1 = 0.5f;
    #pragma unroll 8
    for (int s = 0; s < S_CHUNKS; s++) {
        const float4 c = g_coef[s * B_DIM + b];
        g_state[s * B_DIM + b] = make_float2(p0, p1);
        p0 = fmaf(p0, c.x, c.y);
        p1 = fmaf(p1, c.z, c.w);
    }
}

// ---------------------------------------------------------------------------
// Pass 2 (NEW lean step, same 262144 threads / scalar stores as the 33.4us
// R1 version — only the per-step instruction count changes, ~12 -> ~7).
// Representation: pa = state selected by pb (the lineage being updated),
// po = the other. The step's output IS the next step's pa:
//   u  = fma(r, pa, xb ? lr : 0)      (update of lineage pb)
//   sw = (xb == pb)
//   pa' = sw ? u : po ; po' = sw ? po : u ; store pa'
// Values are bit-identical to the R8 lean math (passed, rel_err 1.22e-5).
// ---------------------------------------------------------------------------
__global__ void __launch_bounds__(256) pass2_kernel(
    float* __restrict__ out, const float* __restrict__ lrp)
{
    const int b = blockIdx.x * blockDim.x + threadIdx.x;
    const int s = blockIdx.y;
    const float lr = clamp_lr(lrp);
    const float r  = 1.0f - lr;

    float* op = out + (size_t)(s * CH) * B_DIM + b;

    const float2 st = g_state[s * B_DIM + b];
    const uint4  bw = g_bits [s * B_DIM + b];
    const uint32_t W[NWORDS] = { bw.x, bw.y, bw.z, bw.w };
    bool pb = (g_xprev[s * B_DIM + b] != 0.0f);

    float pa = pb ? st.y : st.x;     // selected lineage
    float po = pb ? st.x : st.y;     // other lineage

    #pragma unroll
    for (int wi = 0; wi < NWORDS; wi++) {
        const uint32_t w = W[wi];
        #pragma unroll
        for (int i = 0; i < 32; i++) {
            const bool  xb  = (w >> i) & 1u;          // LOP3 -> predicate
            const float add = xb ? lr : 0.0f;
            const float u   = fmaf(r, pa, add);
            const bool  sw  = (xb == pb);             // PLOP3
            const float npa = sw ? u  : po;
            po              = sw ? po : u;
            pa = npa;
            op[(size_t)(wi * 32 + i) * B_DIM] = pa;   // output == next selected
            pb = xb;
        }
    }
}

extern "C" void kernel_launch(void* const* d_in, const int* in_sizes, int n_in,
                              void* d_out, int out_size)
{
    const float* x  = (const float*)d_in[0];
    const float* lr = (const float*)d_in[1];
    if (n_in >= 2 && in_sizes[0] == 1) { x = (const float*)d_in[1]; lr = (const float*)d_in[0]; }

    dim3 blk(256);

    pass1_kernel<<<dim3(B_DIM / 256, S_CHUNKS), blk>>>(x, lr);
    scan_kernel<<<B_DIM / 256, blk>>>();
    pass2_kernel<<<dim3(B_DIM / 256, S_CHUNKS), blk>>>((float*)d_out, lr);
}